// round 11
// baseline (speedup 1.0000x reference)
#include <cuda_runtime.h>
#include <math.h>

namespace {

constexpr int B    = 4;
constexpr int S    = 2048;
constexpr int DIN  = 1024;
constexpr int DOUT = 1024;
constexpr int NH   = 16;
constexpr int HD   = 64;
constexpr int M    = B * S;            // 8192 rows

// ---- scratch (static device memory: allowed) ----
__device__ float g_q[(size_t)B * NH * S * HD];    // [B,H,S,HD] tf32-rounded
__device__ float g_k[(size_t)B * NH * S * HD];
__device__ float g_v[(size_t)B * NH * S * HD];
__device__ float g_ctx[(size_t)M * DOUT];         // [B*S, DOUT] tf32-rounded
__device__ float g_xc[(size_t)M * DIN];           // tf32-rounded x
__device__ float g_wq[(size_t)DOUT * DIN];
__device__ float g_wk[(size_t)DOUT * DIN];
__device__ float g_wv[(size_t)DOUT * DIN];
__device__ float g_wo[(size_t)DOUT * DOUT];

__device__ __forceinline__ unsigned f2tf32(float x) {
    unsigned u;
    asm("cvt.rna.tf32.f32 %0, %1;" : "=r"(u) : "f"(x));
    return u;
}
__device__ __forceinline__ float tf(float x) { return __uint_as_float(f2tf32(x)); }

__device__ __forceinline__ void cp16(void* smem_dst, const void* gmem_src) {
    unsigned s = (unsigned)__cvta_generic_to_shared(smem_dst);
    asm volatile("cp.async.ca.shared.global [%0], [%1], 16;" :: "r"(s), "l"(gmem_src));
}
__device__ __forceinline__ void cp_commit() {
    asm volatile("cp.async.commit_group;");
}
__device__ __forceinline__ void cp_wait0() {
    asm volatile("cp.async.wait_group 0;");
}

__device__ __forceinline__ void mma_tf32(
    float& c0, float& c1, float& c2, float& c3,
    unsigned a0, unsigned a1, unsigned a2, unsigned a3,
    unsigned b0, unsigned b1)
{
    asm volatile(
        "mma.sync.aligned.m16n8k8.row.col.f32.tf32.tf32.f32 "
        "{%0,%1,%2,%3}, {%4,%5,%6,%7}, {%8,%9}, {%0,%1,%2,%3};"
        : "+f"(c0), "+f"(c1), "+f"(c2), "+f"(c3)
        : "r"(a0), "r"(a1), "r"(a2), "r"(a3), "r"(b0), "r"(b1));
}

// ============================================================
// Fused tf32 rounding pre-pass (plain layout, one launch)
// ============================================================
constexpr int XB = M * DIN / 4 / 256;     // 8192 blocks for x
constexpr int WB = DOUT * DIN / 4 / 256;  // 1024 blocks per weight

__global__ __launch_bounds__(256) void cvt_all_kernel(
    const float* __restrict__ x,  float* __restrict__ xc,
    const float* __restrict__ Wq, float* __restrict__ wq,
    const float* __restrict__ Wk, float* __restrict__ wk,
    const float* __restrict__ Wv, float* __restrict__ wv,
    const float* __restrict__ Wo, float* __restrict__ wo)
{
    int b = blockIdx.x;
    const float* src;
    float* dst;
    int rel;
    if (b < XB) { src = x; dst = xc; rel = b; }
    else {
        int w = (b - XB) >> 10;           // WB = 1024
        rel = (b - XB) & 1023;
        src = (w == 0) ? Wq : (w == 1) ? Wk : (w == 2) ? Wv : Wo;
        dst = (w == 0) ? wq : (w == 1) ? wk : (w == 2) ? wv : wo;
    }
    int i = rel * 256 + threadIdx.x;
    float4 v = reinterpret_cast<const float4*>(src)[i];
    v.x = tf(v.x); v.y = tf(v.y); v.z = tf(v.z); v.w = tf(v.w);
    reinterpret_cast<float4*>(dst)[i] = v;
}

// ============================================================
// TF32 GEMM v7: cp.async, block 128x128, BK=32, 512 threads.
// 16 warps 4(m)x4(n), warp tile 32x32 -> 2x warps/SM vs v5.
// ============================================================
constexpr int GBM = 128, GBN = 128, GBK = 32, GPAD = 36;
constexpr size_t GEMM_SMEM = (size_t)(2 * GBM * GPAD + 2 * GBN * GPAD) * sizeof(float); // 73728

__device__ __forceinline__ void gemm_body(
    const float* __restrict__ A, const float* __restrict__ W,
    float* __restrict__ C, const float* __restrict__ bias,
    int K, int N, int head_layout, float* sm)
{
    float* sA = sm;
    float* sW = sm + 2 * GBM * GPAD;

    const int tid  = threadIdx.x;
    const int m0   = blockIdx.y * GBM;
    const int n0   = blockIdx.x * GBN;
    const int warp = tid >> 5, lane = tid & 31;
    const int wm = (warp >> 2) * 32;      // 0,32,64,96
    const int wn = (warp & 3) * 32;       // 0,32,64,96
    const int lr = lane >> 2, lc = lane & 3;

    auto issue_cp = [&](int buf, int k0) {
        float* dA = sA + buf * GBM * GPAD;
        float* dW = sW + buf * GBN * GPAD;
#pragma unroll
        for (int p = 0; p < 2; p++) {
            int idx = p * 512 + tid;
            int row = idx >> 3, c4 = (idx & 7) << 2;
            cp16(dA + row * GPAD + c4, A + (size_t)(m0 + row) * K + k0 + c4);
            cp16(dW + row * GPAD + c4, W + (size_t)(n0 + row) * K + k0 + c4);
        }
        cp_commit();
    };

    float acc[2][4][4] = {};

    issue_cp(0, 0);
    const int NIT = K / GBK;
    for (int it = 0; it < NIT; ++it) {
        cp_wait0();
        __syncthreads();
        if (it + 1 < NIT) issue_cp((it + 1) & 1, (it + 1) * GBK);

        const float* bA = sA + (it & 1) * GBM * GPAD;
        const float* bW = sW + (it & 1) * GBN * GPAD;
#pragma unroll
        for (int kk = 0; kk < GBK; kk += 8) {
            unsigned af[2][4], bf[4][2];
#pragma unroll
            for (int mt = 0; mt < 2; mt++) {
                int r = wm + mt * 16 + lr;
                af[mt][0] = __float_as_uint(bA[r * GPAD + kk + lc]);
                af[mt][1] = __float_as_uint(bA[(r + 8) * GPAD + kk + lc]);
                af[mt][2] = __float_as_uint(bA[r * GPAD + kk + lc + 4]);
                af[mt][3] = __float_as_uint(bA[(r + 8) * GPAD + kk + lc + 4]);
            }
#pragma unroll
            for (int nt = 0; nt < 4; nt++) {
                int c = wn + nt * 8 + lr;
                bf[nt][0] = __float_as_uint(bW[c * GPAD + kk + lc]);
                bf[nt][1] = __float_as_uint(bW[c * GPAD + kk + lc + 4]);
            }
#pragma unroll
            for (int mt = 0; mt < 2; mt++)
#pragma unroll
                for (int nt = 0; nt < 4; nt++)
                    mma_tf32(acc[mt][nt][0], acc[mt][nt][1], acc[mt][nt][2], acc[mt][nt][3],
                             af[mt][0], af[mt][1], af[mt][2], af[mt][3],
                             bf[nt][0], bf[nt][1]);
        }
        __syncthreads();    // all reads of this buf done before refill
    }

#pragma unroll
    for (int mt = 0; mt < 2; mt++) {
#pragma unroll
        for (int i = 0; i < 2; i++) {
            int m = m0 + wm + mt * 16 + lr + i * 8;
#pragma unroll
            for (int nt = 0; nt < 4; nt++) {
                int n = n0 + wn + nt * 8 + lc * 2;
                float v0 = acc[mt][nt][i * 2 + 0];
                float v1 = acc[mt][nt][i * 2 + 1];
                if (bias) { v0 += bias[n]; v1 += bias[n + 1]; }
                if (!head_layout) {
                    *reinterpret_cast<float2*>(&C[(size_t)m * N + n]) = make_float2(v0, v1);
                } else {
                    int h = n >> 6, d = n & 63;
                    int bb = m >> 11, ss = m & 2047;
                    *reinterpret_cast<float2*>(
                        &C[(((size_t)(bb * NH + h) * S) + ss) * HD + d]) =
                        make_float2(tf(v0), tf(v1));   // pre-round for attention
                }
            }
        }
    }
}

__global__ __launch_bounds__(512, 2) void qkv_gemm_kernel(
    const float* __restrict__ A,
    const float* __restrict__ Wq, const float* __restrict__ Wk, const float* __restrict__ Wv,
    float* __restrict__ q, float* __restrict__ k, float* __restrict__ v)
{
    extern __shared__ float sm[];
    const int z = blockIdx.z;
    const float* W = (z == 0) ? Wq : (z == 1) ? Wk : Wv;
    float* C       = (z == 0) ? q  : (z == 1) ? k  : v;
    gemm_body(A, W, C, nullptr, DIN, DOUT, 1, sm);
}

__global__ __launch_bounds__(512, 2) void out_gemm_kernel(
    const float* __restrict__ A, const float* __restrict__ W,
    float* __restrict__ C, const float* __restrict__ bias)
{
    extern __shared__ float sm[];
    gemm_body(A, W, C, bias, DOUT, DOUT, 0, sm);
}

// ============================================================
// Causal flash attention: BQ=128, BKV=64, 512 threads (16 warps
// 4(m)x4(n), warp tile 32x16). cp.async K/V, in-reg softmax.
// ============================================================
constexpr int BQ  = 128;
constexpr int BKV = 64;
constexpr int PAD = 68;
constexpr float LOG2E = 1.4426950408889634f;
constexpr size_t ATTN_SMEM = (size_t)(BQ + BKV + BKV + BQ) * PAD * sizeof(float); // 104448

__global__ __launch_bounds__(512, 2) void attn_kernel(
    const float* __restrict__ Q, const float* __restrict__ Kp,
    const float* __restrict__ Vp, float* __restrict__ ctx)
{
    extern __shared__ float sm[];
    float (*Qs)[PAD] = reinterpret_cast<float(*)[PAD]>(sm);
    float (*Ks)[PAD] = reinterpret_cast<float(*)[PAD]>(sm + BQ * PAD);
    float (*Vs)[PAD] = reinterpret_cast<float(*)[PAD]>(sm + (BQ + BKV) * PAD);
    float (*Ps)[PAD] = reinterpret_cast<float(*)[PAD]>(sm + (BQ + 2 * BKV) * PAD);

    __shared__ float m_s[BQ], l_s[BQ];
    __shared__ float pmax[BQ][4], psum[BQ][4];

    const int tid  = threadIdx.x;
    const int warp = tid >> 5, lane = tid & 31;
    const int wm = (warp >> 2) * 32;      // 0,32,64,96  (m rows)
    const int wn = (warp & 3) * 16;       // 0,16,32,48  (n cols)
    const int wi = warp & 3;
    const int lr = lane >> 2, lc = lane & 3;
    const int qt = blockIdx.x;
    const int bh = blockIdx.y;

    const float* qb = Q  + (size_t)bh * S * HD + (size_t)qt * BQ * HD;
    const float* kb = Kp + (size_t)bh * S * HD;
    const float* vb = Vp + (size_t)bh * S * HD;

    const float qscale = 0.125f * LOG2E;
    for (int i = tid; i < BQ * HD / 4; i += 512) {
        int row = i >> 4;
        int c4  = (i & 15) << 2;
        float4 v = *reinterpret_cast<const float4*>(qb + row * HD + c4);
        Qs[row][c4 + 0] = tf(v.x * qscale);
        Qs[row][c4 + 1] = tf(v.y * qscale);
        Qs[row][c4 + 2] = tf(v.z * qscale);
        Qs[row][c4 + 3] = tf(v.w * qscale);
    }
    if (tid < BQ) { m_s[tid] = -1e30f; l_s[tid] = 0.f; }

    float acc_o[2][2][4] = {};
    __syncthreads();

    const int NKT = 2 * qt + 2;
    for (int kt = 0; kt < NKT; kt++) {
        const float* kp_ = kb + (size_t)kt * BKV * HD;
        const float* vp_ = vb + (size_t)kt * BKV * HD;
#pragma unroll
        for (int p = 0; p < 2; p++) {
            int i = p * 512 + tid;
            int row = i >> 4, c4 = (i & 15) << 2;
            cp16(&Ks[row][c4], kp_ + row * HD + c4);
            cp16(&Vs[row][c4], vp_ + row * HD + c4);
        }
        cp_commit();
        cp_wait0();
        __syncthreads();                                   // sync 1

        // ---- scores: S = Qs @ Ks^T (warp tile 32x16) ----
        float acc_s[2][2][4] = {};
#pragma unroll
        for (int kk = 0; kk < HD; kk += 8) {
            unsigned af[2][4], bf[2][2];
#pragma unroll
            for (int mt = 0; mt < 2; mt++) {
                int r = wm + mt * 16 + lr;
                af[mt][0] = __float_as_uint(Qs[r][kk + lc]);
                af[mt][1] = __float_as_uint(Qs[r + 8][kk + lc]);
                af[mt][2] = __float_as_uint(Qs[r][kk + lc + 4]);
                af[mt][3] = __float_as_uint(Qs[r + 8][kk + lc + 4]);
            }
#pragma unroll
            for (int nt = 0; nt < 2; nt++) {
                int c = wn + nt * 8 + lr;
                bf[nt][0] = __float_as_uint(Ks[c][kk + lc]);
                bf[nt][1] = __float_as_uint(Ks[c][kk + lc + 4]);
            }
#pragma unroll
            for (int mt = 0; mt < 2; mt++)
#pragma unroll
                for (int nt = 0; nt < 2; nt++)
                    mma_tf32(acc_s[mt][nt][0], acc_s[mt][nt][1],
                             acc_s[mt][nt][2], acc_s[mt][nt][3],
                             af[mt][0], af[mt][1], af[mt][2], af[mt][3],
                             bf[nt][0], bf[nt][1]);
        }

        // ---- causal mask ----
        if (kt >= 2 * qt) {
            int cbase = kt * BKV - qt * BQ;
#pragma unroll
            for (int mt = 0; mt < 2; mt++) {
                int r0 = wm + mt * 16 + lr;
#pragma unroll
                for (int nt = 0; nt < 2; nt++) {
                    int c0 = cbase + wn + nt * 8 + 2 * lc;
                    if (c0 > r0)         acc_s[mt][nt][0] = -1e30f;
                    if (c0 + 1 > r0)     acc_s[mt][nt][1] = -1e30f;
                    if (c0 > r0 + 8)     acc_s[mt][nt][2] = -1e30f;
                    if (c0 + 1 > r0 + 8) acc_s[mt][nt][3] = -1e30f;
                }
            }
        }

        // ---- warp-local row max over this warp's 16 cols ----
#pragma unroll
        for (int mt = 0; mt < 2; mt++) {
            float m0 = -1e30f, m1 = -1e30f;
#pragma unroll
            for (int nt = 0; nt < 2; nt++) {
                m0 = fmaxf(m0, fmaxf(acc_s[mt][nt][0], acc_s[mt][nt][1]));
                m1 = fmaxf(m1, fmaxf(acc_s[mt][nt][2], acc_s[mt][nt][3]));
            }
            m0 = fmaxf(m0, __shfl_xor_sync(0xffffffffu, m0, 1));
            m0 = fmaxf(m0, __shfl_xor_sync(0xffffffffu, m0, 2));
            m1 = fmaxf(m1, __shfl_xor_sync(0xffffffffu, m1, 1));
            m1 = fmaxf(m1, __shfl_xor_sync(0xffffffffu, m1, 2));
            if (lc == 0) {
                pmax[wm + mt * 16 + lr][wi] = m0;
                pmax[wm + mt * 16 + lr + 8][wi] = m1;
            }
        }
        __syncthreads();                                   // sync 2

        // ---- exp2 in regs, write tf32 P, partial sums ----
        float alpha[2][2], mxv[2][2];
#pragma unroll
        for (int mt = 0; mt < 2; mt++) {
#pragma unroll
            for (int i = 0; i < 2; i++) {
                int r = wm + mt * 16 + lr + i * 8;
                float mo = m_s[r];
                float mx = fmaxf(fmaxf(mo, fmaxf(pmax[r][0], pmax[r][1])),
                                 fmaxf(pmax[r][2], pmax[r][3]));
                mxv[mt][i] = mx;
                alpha[mt][i] = exp2f(mo - mx);
                float sum = 0.f;
#pragma unroll
                for (int nt = 0; nt < 2; nt++) {
                    float p0 = tf(exp2f(acc_s[mt][nt][i * 2 + 0] - mx));
                    float p1 = tf(exp2f(acc_s[mt][nt][i * 2 + 1] - mx));
                    sum += p0 + p1;
                    *reinterpret_cast<float2*>(&Ps[r][wn + nt * 8 + 2 * lc]) =
                        make_float2(p0, p1);
                }
                sum += __shfl_xor_sync(0xffffffffu, sum, 1);
                sum += __shfl_xor_sync(0xffffffffu, sum, 2);
                if (lc == 0) psum[r][wi] = sum;
            }
        }
        __syncthreads();                                   // sync 3

        // ---- state update, rescale O, PV mma ----
        if (wi == 0 && lc == 0) {
#pragma unroll
            for (int mt = 0; mt < 2; mt++)
#pragma unroll
                for (int i = 0; i < 2; i++) {
                    int r = wm + mt * 16 + lr + i * 8;
                    l_s[r] = l_s[r] * alpha[mt][i] +
                             (psum[r][0] + psum[r][1]) + (psum[r][2] + psum[r][3]);
                    m_s[r] = mxv[mt][i];
                }
        }
#pragma unroll
        for (int mt = 0; mt < 2; mt++)
#pragma unroll
            for (int nt = 0; nt < 2; nt++) {
                acc_o[mt][nt][0] *= alpha[mt][0]; acc_o[mt][nt][1] *= alpha[mt][0];
                acc_o[mt][nt][2] *= alpha[mt][1]; acc_o[mt][nt][3] *= alpha[mt][1];
            }
#pragma unroll
        for (int kk = 0; kk < BKV; kk += 8) {
            unsigned af[2][4], bf[2][2];
#pragma unroll
            for (int mt = 0; mt < 2; mt++) {
                int r = wm + mt * 16 + lr;
                af[mt][0] = __float_as_uint(Ps[r][kk + lc]);
                af[mt][1] = __float_as_uint(Ps[r + 8][kk + lc]);
                af[mt][2] = __float_as_uint(Ps[r][kk + lc + 4]);
                af[mt][3] = __float_as_uint(Ps[r + 8][kk + lc + 4]);
            }
#pragma unroll
            for (int nt = 0; nt < 2; nt++) {
                int c = wn + nt * 8 + lr;
                bf[nt][0] = __float_as_uint(Vs[kk + lc][c]);
                bf[nt][1] = __float_as_uint(Vs[kk + lc + 4][c]);
            }
#pragma unroll
            for (int mt = 0; mt < 2; mt++)
#pragma unroll
                for (int nt = 0; nt < 2; nt++)
                    mma_tf32(acc_o[mt][nt][0], acc_o[mt][nt][1],
                             acc_o[mt][nt][2], acc_o[mt][nt][3],
                             af[mt][0], af[mt][1], af[mt][2], af[mt][3],
                             bf[nt][0], bf[nt][1]);
        }
        __syncthreads();                                   // sync 4
    }

    // epilogue: normalize, round to tf32 (feeds Wo GEMM), write ctx
    const int h  = bh % NH;
    const int bb = bh / NH;
#pragma unroll
    for (int mt = 0; mt < 2; mt++) {
#pragma unroll
        for (int i = 0; i < 2; i++) {
            int r = wm + mt * 16 + lr + i * 8;
            float inv = 1.0f / l_s[r];
            size_t rowp = (size_t)(bb * S + qt * BQ + r) * DOUT + h * HD;
#pragma unroll
            for (int nt = 0; nt < 2; nt++) {
                int c = wn + nt * 8 + lc * 2;
                *reinterpret_cast<float2*>(&ctx[rowp + c]) =
                    make_float2(tf(acc_o[mt][nt][i * 2 + 0] * inv),
                                tf(acc_o[mt][nt][i * 2 + 1] * inv));
            }
        }
    }
}

}  // namespace

extern "C" void kernel_launch(void* const* d_in, const int* in_sizes, int n_in,
                              void* d_out, int out_size)
{
    (void)in_sizes; (void)n_in; (void)out_size;
    const float* x  = (const float*)d_in[0];
    const float* Wq = (const float*)d_in[1];
    const float* Wk = (const float*)d_in[2];
    const float* Wv = (const float*)d_in[3];
    const float* Wo = (const float*)d_in[4];
    const float* bo = (const float*)d_in[5];
    float* out = (float*)d_out;

    float *qp, *kp, *vp, *cp, *xc, *wq, *wk, *wv, *wo;
    cudaGetSymbolAddress((void**)&qp, g_q);
    cudaGetSymbolAddress((void**)&kp, g_k);
    cudaGetSymbolAddress((void**)&vp, g_v);
    cudaGetSymbolAddress((void**)&cp, g_ctx);
    cudaGetSymbolAddress((void**)&xc, g_xc);
    cudaGetSymbolAddress((void**)&wq, g_wq);
    cudaGetSymbolAddress((void**)&wk, g_wk);
    cudaGetSymbolAddress((void**)&wv, g_wv);
    cudaGetSymbolAddress((void**)&wo, g_wo);

    cudaFuncSetAttribute(qkv_gemm_kernel,
                         cudaFuncAttributeMaxDynamicSharedMemorySize, (int)GEMM_SMEM);
    cudaFuncSetAttribute(out_gemm_kernel,
                         cudaFuncAttributeMaxDynamicSharedMemorySize, (int)GEMM_SMEM);
    cudaFuncSetAttribute(attn_kernel,
                         cudaFuncAttributeMaxDynamicSharedMemorySize, (int)ATTN_SMEM);

    // ---- fused tf32 rounding pre-pass (1 launch) ----
    cvt_all_kernel<<<XB + 4 * WB, 256>>>(x, xc, Wq, wq, Wk, wk, Wv, wv, Wo, wo);

    // ---- fused QKV projections (outputs tf32-rounded) ----
    dim3 qkv_grid(DOUT / GBN, M / GBM, 3);  // (8, 64, 3)
    qkv_gemm_kernel<<<qkv_grid, 512, GEMM_SMEM>>>(xc, wq, wk, wv, qp, kp, vp);

    // ---- attention ----
    dim3 attn_grid(S / BQ, B * NH);         // (16, 64)
    attn_kernel<<<attn_grid, 512, ATTN_SMEM>>>(qp, kp, vp, cp);

    // ---- output projection ----
    dim3 out_grid(DOUT / GBN, M / GBM);     // (8, 64)
    out_gemm_kernel<<<out_grid, 512, GEMM_SMEM>>>(cp, wo, out, bo);
}

// round 16
// speedup vs baseline: 1.0662x; 1.0662x over previous
#include <cuda_runtime.h>
#include <math.h>

namespace {

constexpr int B    = 4;
constexpr int S    = 2048;
constexpr int DIN  = 1024;
constexpr int DOUT = 1024;
constexpr int NH   = 16;
constexpr int HD   = 64;
constexpr int M    = B * S;            // 8192 rows

// ---- scratch (static device memory: allowed) ----
__device__ float g_q[(size_t)B * NH * S * HD];    // [B,H,S,HD] tf32-rounded
__device__ float g_k[(size_t)B * NH * S * HD];
__device__ float g_v[(size_t)B * NH * S * HD];
__device__ float g_ctx[(size_t)M * DOUT];         // [B*S, DOUT] tf32-rounded
__device__ float g_xc[(size_t)M * DIN];           // tf32-rounded x
__device__ float g_wq[(size_t)DOUT * DIN];
__device__ float g_wk[(size_t)DOUT * DIN];
__device__ float g_wv[(size_t)DOUT * DIN];
__device__ float g_wo[(size_t)DOUT * DOUT];

__device__ __forceinline__ unsigned f2tf32(float x) {
    unsigned u;
    asm("cvt.rna.tf32.f32 %0, %1;" : "=r"(u) : "f"(x));
    return u;
}
__device__ __forceinline__ float tf(float x) { return __uint_as_float(f2tf32(x)); }

__device__ __forceinline__ void cp16(void* smem_dst, const void* gmem_src) {
    unsigned s = (unsigned)__cvta_generic_to_shared(smem_dst);
    asm volatile("cp.async.ca.shared.global [%0], [%1], 16;" :: "r"(s), "l"(gmem_src));
}
__device__ __forceinline__ void cp_commit() {
    asm volatile("cp.async.commit_group;");
}
__device__ __forceinline__ void cp_wait0() {
    asm volatile("cp.async.wait_group 0;");
}

__device__ __forceinline__ void mma_tf32(
    float& c0, float& c1, float& c2, float& c3,
    unsigned a0, unsigned a1, unsigned a2, unsigned a3,
    unsigned b0, unsigned b1)
{
    asm volatile(
        "mma.sync.aligned.m16n8k8.row.col.f32.tf32.tf32.f32 "
        "{%0,%1,%2,%3}, {%4,%5,%6,%7}, {%8,%9}, {%0,%1,%2,%3};"
        : "+f"(c0), "+f"(c1), "+f"(c2), "+f"(c3)
        : "r"(a0), "r"(a1), "r"(a2), "r"(a3), "r"(b0), "r"(b1));
}

// ============================================================
// Fused tf32 rounding pre-pass (plain layout, one launch)
// ============================================================
constexpr int XB = M * DIN / 4 / 256;     // 8192 blocks for x
constexpr int WB = DOUT * DIN / 4 / 256;  // 1024 blocks per weight

__global__ __launch_bounds__(256) void cvt_all_kernel(
    const float* __restrict__ x,  float* __restrict__ xc,
    const float* __restrict__ Wq, float* __restrict__ wq,
    const float* __restrict__ Wk, float* __restrict__ wk,
    const float* __restrict__ Wv, float* __restrict__ wv,
    const float* __restrict__ Wo, float* __restrict__ wo)
{
    int b = blockIdx.x;
    const float* src;
    float* dst;
    int rel;
    if (b < XB) { src = x; dst = xc; rel = b; }
    else {
        int w = (b - XB) >> 10;           // WB = 1024
        rel = (b - XB) & 1023;
        src = (w == 0) ? Wq : (w == 1) ? Wk : (w == 2) ? Wv : Wo;
        dst = (w == 0) ? wq : (w == 1) ? wk : (w == 2) ? wv : wo;
    }
    int i = rel * 256 + threadIdx.x;
    float4 v = reinterpret_cast<const float4*>(src)[i];
    v.x = tf(v.x); v.y = tf(v.y); v.z = tf(v.z); v.w = tf(v.w);
    reinterpret_cast<float4*>(dst)[i] = v;
}

// ============================================================
// TF32 GEMM: cp.async, block tile 128x64, BK=32, 8 warps 4(m)x2(n),
// warp tile 32x32 (64 regs). launch_bounds(256,4): 64 regs x 1024 thr
// = full RF, smem 4x55.3KB = 221KB -> 4 CTAs/SM (2x warps vs R9).
// ============================================================
constexpr int GBM = 128, GBN = 64, GBK = 32, GPAD = 36;
constexpr size_t GEMM_SMEM = (size_t)(2 * GBM * GPAD + 2 * GBN * GPAD) * sizeof(float); // 55296

__device__ __forceinline__ void gemm_body(
    const float* __restrict__ A, const float* __restrict__ W,
    float* __restrict__ C, const float* __restrict__ bias,
    int K, int N, int head_layout, float* sm)
{
    float* sA = sm;
    float* sW = sm + 2 * GBM * GPAD;

    const int tid  = threadIdx.x;
    const int m0   = blockIdx.y * GBM;
    const int n0   = blockIdx.x * GBN;
    const int warp = tid >> 5, lane = tid & 31;
    const int wm = (warp >> 1) * 32;
    const int wn = (warp & 1) * 32;
    const int lr = lane >> 2, lc = lane & 3;

    auto issue_cp = [&](int buf, int k0) {
        float* dA = sA + buf * GBM * GPAD;
        float* dW = sW + buf * GBN * GPAD;
#pragma unroll
        for (int p = 0; p < 4; p++) {
            int idx = p * 256 + tid;
            int row = idx >> 3, c4 = (idx & 7) << 2;
            cp16(dA + row * GPAD + c4, A + (size_t)(m0 + row) * K + k0 + c4);
        }
#pragma unroll
        for (int p = 0; p < 2; p++) {
            int idx = p * 256 + tid;
            int row = idx >> 3, c4 = (idx & 7) << 2;
            cp16(dW + row * GPAD + c4, W + (size_t)(n0 + row) * K + k0 + c4);
        }
        cp_commit();
    };

    float acc[2][4][4] = {};

    issue_cp(0, 0);
    const int NIT = K / GBK;
    for (int it = 0; it < NIT; ++it) {
        cp_wait0();
        __syncthreads();
        if (it + 1 < NIT) issue_cp((it + 1) & 1, (it + 1) * GBK);

        const float* bA = sA + (it & 1) * GBM * GPAD;
        const float* bW = sW + (it & 1) * GBN * GPAD;
#pragma unroll
        for (int kk = 0; kk < GBK; kk += 8) {
            unsigned af[2][4], bf[4][2];
#pragma unroll
            for (int mt = 0; mt < 2; mt++) {
                int r = wm + mt * 16 + lr;
                af[mt][0] = __float_as_uint(bA[r * GPAD + kk + lc]);
                af[mt][1] = __float_as_uint(bA[(r + 8) * GPAD + kk + lc]);
                af[mt][2] = __float_as_uint(bA[r * GPAD + kk + lc + 4]);
                af[mt][3] = __float_as_uint(bA[(r + 8) * GPAD + kk + lc + 4]);
            }
#pragma unroll
            for (int nt = 0; nt < 4; nt++) {
                int c = wn + nt * 8 + lr;
                bf[nt][0] = __float_as_uint(bW[c * GPAD + kk + lc]);
                bf[nt][1] = __float_as_uint(bW[c * GPAD + kk + lc + 4]);
            }
#pragma unroll
            for (int mt = 0; mt < 2; mt++)
#pragma unroll
                for (int nt = 0; nt < 4; nt++)
                    mma_tf32(acc[mt][nt][0], acc[mt][nt][1], acc[mt][nt][2], acc[mt][nt][3],
                             af[mt][0], af[mt][1], af[mt][2], af[mt][3],
                             bf[nt][0], bf[nt][1]);
        }
        __syncthreads();    // all reads of this buf done before refill
    }

#pragma unroll
    for (int mt = 0; mt < 2; mt++) {
#pragma unroll
        for (int i = 0; i < 2; i++) {
            int m = m0 + wm + mt * 16 + lr + i * 8;
#pragma unroll
            for (int nt = 0; nt < 4; nt++) {
                int n = n0 + wn + nt * 8 + lc * 2;
                float v0 = acc[mt][nt][i * 2 + 0];
                float v1 = acc[mt][nt][i * 2 + 1];
                if (bias) { v0 += bias[n]; v1 += bias[n + 1]; }
                if (!head_layout) {
                    *reinterpret_cast<float2*>(&C[(size_t)m * N + n]) = make_float2(v0, v1);
                } else {
                    int h = n >> 6, d = n & 63;
                    int bb = m >> 11, ss = m & 2047;
                    *reinterpret_cast<float2*>(
                        &C[(((size_t)(bb * NH + h) * S) + ss) * HD + d]) =
                        make_float2(tf(v0), tf(v1));   // pre-round for attention
                }
            }
        }
    }
}

__global__ __launch_bounds__(256, 4) void qkv_gemm_kernel(
    const float* __restrict__ A,
    const float* __restrict__ Wq, const float* __restrict__ Wk, const float* __restrict__ Wv,
    float* __restrict__ q, float* __restrict__ k, float* __restrict__ v)
{
    extern __shared__ float sm[];
    const int z = blockIdx.z;
    const float* W = (z == 0) ? Wq : (z == 1) ? Wk : Wv;
    float* C       = (z == 0) ? q  : (z == 1) ? k  : v;
    gemm_body(A, W, C, nullptr, DIN, DOUT, 1, sm);
}

__global__ __launch_bounds__(256, 4) void out_gemm_kernel(
    const float* __restrict__ A, const float* __restrict__ W,
    float* __restrict__ C, const float* __restrict__ bias)
{
    extern __shared__ float sm[];
    gemm_body(A, W, C, bias, DOUT, DOUT, 0, sm);
}

// ============================================================
// Causal flash attention: BQ=128, BKV=64, cp.async K/V with
// K-prefetch overlapped into the PV mma; in-register softmax;
// qt REVERSED so long (high-qt) blocks are scheduled first.
// ============================================================
constexpr int BQ  = 128;
constexpr int BKV = 64;
constexpr int PAD = 68;
constexpr float LOG2E = 1.4426950408889634f;
constexpr size_t ATTN_SMEM = (size_t)(BQ + BKV + BKV + BQ) * PAD * sizeof(float); // 104448

__global__ __launch_bounds__(256, 2) void attn_kernel(
    const float* __restrict__ Q, const float* __restrict__ Kp,
    const float* __restrict__ Vp, float* __restrict__ ctx)
{
    extern __shared__ float sm[];
    float (*Qs)[PAD] = reinterpret_cast<float(*)[PAD]>(sm);
    float (*Ks)[PAD] = reinterpret_cast<float(*)[PAD]>(sm + BQ * PAD);
    float (*Vs)[PAD] = reinterpret_cast<float(*)[PAD]>(sm + (BQ + BKV) * PAD);
    float (*Ps)[PAD] = reinterpret_cast<float(*)[PAD]>(sm + (BQ + 2 * BKV) * PAD);

    __shared__ float m_s[BQ], l_s[BQ];
    __shared__ float pmax[BQ][2], psum[BQ][2];

    const int tid  = threadIdx.x;
    const int warp = tid >> 5, lane = tid & 31;
    const int wm = (warp >> 1) * 32;
    const int wn = (warp & 1) * 32;
    const int wi = warp & 1;
    const int lr = lane >> 2, lc = lane & 3;
    const int qt = (gridDim.x - 1) - blockIdx.x;   // long blocks first
    const int bh = blockIdx.y;

    const float* qb = Q  + (size_t)bh * S * HD + (size_t)qt * BQ * HD;
    const float* kb = Kp + (size_t)bh * S * HD;
    const float* vb = Vp + (size_t)bh * S * HD;

    auto load_k = [&](int kt) {
        const float* kp_ = kb + (size_t)kt * BKV * HD;
#pragma unroll
        for (int p = 0; p < 4; p++) {
            int i = p * 256 + tid;
            int row = i >> 4, c4 = (i & 15) << 2;
            cp16(&Ks[row][c4], kp_ + row * HD + c4);
        }
        cp_commit();
    };
    auto load_v = [&](int kt) {
        const float* vp_ = vb + (size_t)kt * BKV * HD;
#pragma unroll
        for (int p = 0; p < 4; p++) {
            int i = p * 256 + tid;
            int row = i >> 4, c4 = (i & 15) << 2;
            cp16(&Vs[row][c4], vp_ + row * HD + c4);
        }
        cp_commit();
    };

    const float qscale = 0.125f * LOG2E;
    for (int i = tid; i < BQ * HD / 4; i += 256) {
        int row = i >> 4;
        int c4  = (i & 15) << 2;
        float4 v = *reinterpret_cast<const float4*>(qb + row * HD + c4);
        Qs[row][c4 + 0] = tf(v.x * qscale);
        Qs[row][c4 + 1] = tf(v.y * qscale);
        Qs[row][c4 + 2] = tf(v.z * qscale);
        Qs[row][c4 + 3] = tf(v.w * qscale);
    }
    if (tid < BQ) { m_s[tid] = -1e30f; l_s[tid] = 0.f; }

    float acc_o[2][4][4] = {};
    const int NKT = 2 * qt + 2;

    load_k(0);
    load_v(0);

    for (int kt = 0; kt < NKT; kt++) {
        cp_wait0();
        __syncthreads();                                   // sync 1

        float acc_s[2][4][4] = {};
#pragma unroll
        for (int kk = 0; kk < HD; kk += 8) {
            unsigned af[2][4], bf[4][2];
#pragma unroll
            for (int mt = 0; mt < 2; mt++) {
                int r = wm + mt * 16 + lr;
                af[mt][0] = __float_as_uint(Qs[r][kk + lc]);
                af[mt][1] = __float_as_uint(Qs[r + 8][kk + lc]);
                af[mt][2] = __float_as_uint(Qs[r][kk + lc + 4]);
                af[mt][3] = __float_as_uint(Qs[r + 8][kk + lc + 4]);
            }
#pragma unroll
            for (int nt = 0; nt < 4; nt++) {
                int c = wn + nt * 8 + lr;
                bf[nt][0] = __float_as_uint(Ks[c][kk + lc]);
                bf[nt][1] = __float_as_uint(Ks[c][kk + lc + 4]);
            }
#pragma unroll
            for (int mt = 0; mt < 2; mt++)
#pragma unroll
                for (int nt = 0; nt < 4; nt++)
                    mma_tf32(acc_s[mt][nt][0], acc_s[mt][nt][1],
                             acc_s[mt][nt][2], acc_s[mt][nt][3],
                             af[mt][0], af[mt][1], af[mt][2], af[mt][3],
                             bf[nt][0], bf[nt][1]);
        }

        if (kt >= 2 * qt) {
            int cbase = kt * BKV - qt * BQ;
#pragma unroll
            for (int mt = 0; mt < 2; mt++) {
                int r0 = wm + mt * 16 + lr;
#pragma unroll
                for (int nt = 0; nt < 4; nt++) {
                    int c0 = cbase + wn + nt * 8 + 2 * lc;
                    if (c0 > r0)         acc_s[mt][nt][0] = -1e30f;
                    if (c0 + 1 > r0)     acc_s[mt][nt][1] = -1e30f;
                    if (c0 > r0 + 8)     acc_s[mt][nt][2] = -1e30f;
                    if (c0 + 1 > r0 + 8) acc_s[mt][nt][3] = -1e30f;
                }
            }
        }

#pragma unroll
        for (int mt = 0; mt < 2; mt++) {
            float m0 = -1e30f, m1 = -1e30f;
#pragma unroll
            for (int nt = 0; nt < 4; nt++) {
                m0 = fmaxf(m0, fmaxf(acc_s[mt][nt][0], acc_s[mt][nt][1]));
                m1 = fmaxf(m1, fmaxf(acc_s[mt][nt][2], acc_s[mt][nt][3]));
            }
            m0 = fmaxf(m0, __shfl_xor_sync(0xffffffffu, m0, 1));
            m0 = fmaxf(m0, __shfl_xor_sync(0xffffffffu, m0, 2));
            m1 = fmaxf(m1, __shfl_xor_sync(0xffffffffu, m1, 1));
            m1 = fmaxf(m1, __shfl_xor_sync(0xffffffffu, m1, 2));
            if (lc == 0) {
                pmax[wm + mt * 16 + lr][wi] = m0;
                pmax[wm + mt * 16 + lr + 8][wi] = m1;
            }
        }
        __syncthreads();                                   // sync 2

        float alpha[2][2], mxv[2][2];
#pragma unroll
        for (int mt = 0; mt < 2; mt++) {
#pragma unroll
            for (int i = 0; i < 2; i++) {
                int r = wm + mt * 16 + lr + i * 8;
                float mo = m_s[r];
                float mx = fmaxf(mo, fmaxf(pmax[r][0], pmax[r][1]));
                mxv[mt][i] = mx;
                alpha[mt][i] = exp2f(mo - mx);
                float sum = 0.f;
#pragma unroll
                for (int nt = 0; nt < 4; nt++) {
                    float p0 = tf(exp2f(acc_s[mt][nt][i * 2 + 0] - mx));
                    float p1 = tf(exp2f(acc_s[mt][nt][i * 2 + 1] - mx));
                    sum += p0 + p1;
                    *reinterpret_cast<float2*>(&Ps[r][wn + nt * 8 + 2 * lc]) =
                        make_float2(p0, p1);
                }
                sum += __shfl_xor_sync(0xffffffffu, sum, 1);
                sum += __shfl_xor_sync(0xffffffffu, sum, 2);
                if (lc == 0) psum[r][wi] = sum;
            }
        }
        __syncthreads();                                   // sync 3

        // K no longer needed: overlap next K load with the PV mma
        if (kt + 1 < NKT) load_k(kt + 1);

        if (wi == 0 && lc == 0) {
#pragma unroll
            for (int mt = 0; mt < 2; mt++)
#pragma unroll
                for (int i = 0; i < 2; i++) {
                    int r = wm + mt * 16 + lr + i * 8;
                    l_s[r] = l_s[r] * alpha[mt][i] + psum[r][0] + psum[r][1];
                    m_s[r] = mxv[mt][i];
                }
        }
#pragma unroll
        for (int mt = 0; mt < 2; mt++)
#pragma unroll
            for (int nt = 0; nt < 4; nt++) {
                acc_o[mt][nt][0] *= alpha[mt][0]; acc_o[mt][nt][1] *= alpha[mt][0];
                acc_o[mt][nt][2] *= alpha[mt][1]; acc_o[mt][nt][3] *= alpha[mt][1];
            }
#pragma unroll
        for (int kk = 0; kk < BKV; kk += 8) {
            unsigned af[2][4], bf[4][2];
#pragma unroll
            for (int mt = 0; mt < 2; mt++) {
                int r = wm + mt * 16 + lr;
                af[mt][0] = __float_as_uint(Ps[r][kk + lc]);
                af[mt][1] = __float_as_uint(Ps[r + 8][kk + lc]);
                af[mt][2] = __float_as_uint(Ps[r][kk + lc + 4]);
                af[mt][3] = __float_as_uint(Ps[r + 8][kk + lc + 4]);
            }
#pragma unroll
            for (int nt = 0; nt < 4; nt++) {
                int c = wn + nt * 8 + lr;
                bf[nt][0] = __float_as_uint(Vs[kk + lc][c]);
                bf[nt][1] = __float_as_uint(Vs[kk + lc + 4][c]);
            }
#pragma unroll
            for (int mt = 0; mt < 2; mt++)
#pragma unroll
                for (int nt = 0; nt < 4; nt++)
                    mma_tf32(acc_o[mt][nt][0], acc_o[mt][nt][1],
                             acc_o[mt][nt][2], acc_o[mt][nt][3],
                             af[mt][0], af[mt][1], af[mt][2], af[mt][3],
                             bf[nt][0], bf[nt][1]);
        }
        __syncthreads();                                   // sync 4

        // V free now: issue next V load (waited at loop top)
        if (kt + 1 < NKT) load_v(kt + 1);
    }

    const int h  = bh % NH;
    const int bb = bh / NH;
#pragma unroll
    for (int mt = 0; mt < 2; mt++) {
#pragma unroll
        for (int i = 0; i < 2; i++) {
            int r = wm + mt * 16 + lr + i * 8;
            float inv = 1.0f / l_s[r];
            size_t rowp = (size_t)(bb * S + qt * BQ + r) * DOUT + h * HD;
#pragma unroll
            for (int nt = 0; nt < 4; nt++) {
                int c = wn + nt * 8 + lc * 2;
                *reinterpret_cast<float2*>(&ctx[rowp + c]) =
                    make_float2(tf(acc_o[mt][nt][i * 2 + 0] * inv),
                                tf(acc_o[mt][nt][i * 2 + 1] * inv));
            }
        }
    }
}

}  // namespace

extern "C" void kernel_launch(void* const* d_in, const int* in_sizes, int n_in,
                              void* d_out, int out_size)
{
    (void)in_sizes; (void)n_in; (void)out_size;
    const float* x  = (const float*)d_in[0];
    const float* Wq = (const float*)d_in[1];
    const float* Wk = (const float*)d_in[2];
    const float* Wv = (const float*)d_in[3];
    const float* Wo = (const float*)d_in[4];
    const float* bo = (const float*)d_in[5];
    float* out = (float*)d_out;

    float *qp, *kp, *vp, *cp, *xc, *wq, *wk, *wv, *wo;
    cudaGetSymbolAddress((void**)&qp, g_q);
    cudaGetSymbolAddress((void**)&kp, g_k);
    cudaGetSymbolAddress((void**)&vp, g_v);
    cudaGetSymbolAddress((void**)&cp, g_ctx);
    cudaGetSymbolAddress((void**)&xc, g_xc);
    cudaGetSymbolAddress((void**)&wq, g_wq);
    cudaGetSymbolAddress((void**)&wk, g_wk);
    cudaGetSymbolAddress((void**)&wv, g_wv);
    cudaGetSymbolAddress((void**)&wo, g_wo);

    cudaFuncSetAttribute(qkv_gemm_kernel,
                         cudaFuncAttributeMaxDynamicSharedMemorySize, (int)GEMM_SMEM);
    cudaFuncSetAttribute(out_gemm_kernel,
                         cudaFuncAttributeMaxDynamicSharedMemorySize, (int)GEMM_SMEM);
    cudaFuncSetAttribute(attn_kernel,
                         cudaFuncAttributeMaxDynamicSharedMemorySize, (int)ATTN_SMEM);

    // ---- fused tf32 rounding pre-pass (1 launch) ----
    cvt_all_kernel<<<XB + 4 * WB, 256>>>(x, xc, Wq, wq, Wk, wk, Wv, wv, Wo, wo);

    // ---- fused QKV projections (outputs tf32-rounded) ----
    dim3 qkv_grid(DOUT / GBN, M / GBM, 3);  // (16, 64, 3)
    qkv_gemm_kernel<<<qkv_grid, 256, GEMM_SMEM>>>(xc, wq, wk, wv, qp, kp, vp);

    // ---- attention ----
    dim3 attn_grid(S / BQ, B * NH);         // (16, 64)
    attn_kernel<<<attn_grid, 256, ATTN_SMEM>>>(qp, kp, vp, cp);

    // ---- output projection ----
    dim3 out_grid(DOUT / GBN, M / GBM);     // (16, 64)
    out_gemm_kernel<<<out_grid, 256, GEMM_SMEM>>>(cp, wo, out, bo);
}

// round 17
// speedup vs baseline: 1.1581x; 1.0862x over previous
#include <cuda_runtime.h>
#include <math.h>

namespace {

constexpr int B    = 4;
constexpr int S    = 2048;
constexpr int DIN  = 1024;
constexpr int DOUT = 1024;
constexpr int NH   = 16;
constexpr int HD   = 64;
constexpr int M    = B * S;            // 8192 rows

// ---- scratch (static device memory: allowed) ----
__device__ float g_q[(size_t)B * NH * S * HD];    // [B,H,S,HD] tf32-rounded
__device__ float g_k[(size_t)B * NH * S * HD];
__device__ float g_v[(size_t)B * NH * S * HD];
__device__ float g_ctx[(size_t)M * DOUT];         // [B*S, DOUT] tf32-rounded
__device__ float g_xc[(size_t)M * DIN];           // tf32-rounded x
__device__ float g_wq[(size_t)DOUT * DIN];
__device__ float g_wk[(size_t)DOUT * DIN];
__device__ float g_wv[(size_t)DOUT * DIN];
__device__ float g_wo[(size_t)DOUT * DOUT];

__device__ __forceinline__ unsigned f2tf32(float x) {
    unsigned u;
    asm("cvt.rna.tf32.f32 %0, %1;" : "=r"(u) : "f"(x));
    return u;
}
__device__ __forceinline__ float tf(float x) { return __uint_as_float(f2tf32(x)); }

__device__ __forceinline__ void cp16(void* smem_dst, const void* gmem_src) {
    unsigned s = (unsigned)__cvta_generic_to_shared(smem_dst);
    asm volatile("cp.async.ca.shared.global [%0], [%1], 16;" :: "r"(s), "l"(gmem_src));
}
__device__ __forceinline__ void cp_commit() {
    asm volatile("cp.async.commit_group;");
}
__device__ __forceinline__ void cp_wait0() {
    asm volatile("cp.async.wait_group 0;");
}

__device__ __forceinline__ void mma_tf32(
    float& c0, float& c1, float& c2, float& c3,
    unsigned a0, unsigned a1, unsigned a2, unsigned a3,
    unsigned b0, unsigned b1)
{
    asm volatile(
        "mma.sync.aligned.m16n8k8.row.col.f32.tf32.tf32.f32 "
        "{%0,%1,%2,%3}, {%4,%5,%6,%7}, {%8,%9}, {%0,%1,%2,%3};"
        : "+f"(c0), "+f"(c1), "+f"(c2), "+f"(c3)
        : "r"(a0), "r"(a1), "r"(a2), "r"(a3), "r"(b0), "r"(b1));
}

// ============================================================
// Fused tf32 rounding pre-pass (plain layout, one launch)
// ============================================================
constexpr int XB = M * DIN / 4 / 256;     // 8192 blocks for x
constexpr int WB = DOUT * DIN / 4 / 256;  // 1024 blocks per weight

__global__ __launch_bounds__(256) void cvt_all_kernel(
    const float* __restrict__ x,  float* __restrict__ xc,
    const float* __restrict__ Wq, float* __restrict__ wq,
    const float* __restrict__ Wk, float* __restrict__ wk,
    const float* __restrict__ Wv, float* __restrict__ wv,
    const float* __restrict__ Wo, float* __restrict__ wo)
{
    int b = blockIdx.x;
    const float* src;
    float* dst;
    int rel;
    if (b < XB) { src = x; dst = xc; rel = b; }
    else {
        int w = (b - XB) >> 10;           // WB = 1024
        rel = (b - XB) & 1023;
        src = (w == 0) ? Wq : (w == 1) ? Wk : (w == 2) ? Wv : Wo;
        dst = (w == 0) ? wq : (w == 1) ? wk : (w == 2) ? wv : wo;
    }
    int i = rel * 256 + threadIdx.x;
    float4 v = reinterpret_cast<const float4*>(src)[i];
    v.x = tf(v.x); v.y = tf(v.y); v.z = tf(v.z); v.w = tf(v.w);
    reinterpret_cast<float4*>(dst)[i] = v;
}

// ============================================================
// TF32 GEMM (exact R9 winner): cp.async, block tile 128x128,
// BK=32; 8 warps 4(m)x2(n), warp tile 32x64. 256 threads.
// ============================================================
constexpr int GBM = 128, GBN = 128, GBK = 32, GPAD = 36;
constexpr size_t GEMM_SMEM = (size_t)(2 * GBM * GPAD + 2 * GBN * GPAD) * sizeof(float); // 73728

__device__ __forceinline__ void gemm_body(
    const float* __restrict__ A, const float* __restrict__ W,
    float* __restrict__ C, const float* __restrict__ bias,
    int K, int N, int head_layout, float* sm)
{
    float* sA = sm;
    float* sW = sm + 2 * GBM * GPAD;

    const int tid  = threadIdx.x;
    const int m0   = blockIdx.y * GBM;
    const int n0   = blockIdx.x * GBN;
    const int warp = tid >> 5, lane = tid & 31;
    const int wm = (warp >> 1) * 32;      // 0,32,64,96
    const int wn = (warp & 1) * 64;       // 0,64
    const int lr = lane >> 2, lc = lane & 3;

    auto issue_cp = [&](int buf, int k0) {
        float* dA = sA + buf * GBM * GPAD;
        float* dW = sW + buf * GBN * GPAD;
#pragma unroll
        for (int p = 0; p < 4; p++) {
            int idx = p * 256 + tid;
            int row = idx >> 3, c4 = (idx & 7) << 2;
            cp16(dA + row * GPAD + c4, A + (size_t)(m0 + row) * K + k0 + c4);
            cp16(dW + row * GPAD + c4, W + (size_t)(n0 + row) * K + k0 + c4);
        }
        cp_commit();
    };

    float acc[2][8][4] = {};

    issue_cp(0, 0);
    const int NIT = K / GBK;
    for (int it = 0; it < NIT; ++it) {
        cp_wait0();
        __syncthreads();
        if (it + 1 < NIT) issue_cp((it + 1) & 1, (it + 1) * GBK);

        const float* bA = sA + (it & 1) * GBM * GPAD;
        const float* bW = sW + (it & 1) * GBN * GPAD;
#pragma unroll
        for (int kk = 0; kk < GBK; kk += 8) {
            unsigned af[2][4], bf[8][2];
#pragma unroll
            for (int mt = 0; mt < 2; mt++) {
                int r = wm + mt * 16 + lr;
                af[mt][0] = __float_as_uint(bA[r * GPAD + kk + lc]);
                af[mt][1] = __float_as_uint(bA[(r + 8) * GPAD + kk + lc]);
                af[mt][2] = __float_as_uint(bA[r * GPAD + kk + lc + 4]);
                af[mt][3] = __float_as_uint(bA[(r + 8) * GPAD + kk + lc + 4]);
            }
#pragma unroll
            for (int nt = 0; nt < 8; nt++) {
                int c = wn + nt * 8 + lr;
                bf[nt][0] = __float_as_uint(bW[c * GPAD + kk + lc]);
                bf[nt][1] = __float_as_uint(bW[c * GPAD + kk + lc + 4]);
            }
#pragma unroll
            for (int mt = 0; mt < 2; mt++)
#pragma unroll
                for (int nt = 0; nt < 8; nt++)
                    mma_tf32(acc[mt][nt][0], acc[mt][nt][1], acc[mt][nt][2], acc[mt][nt][3],
                             af[mt][0], af[mt][1], af[mt][2], af[mt][3],
                             bf[nt][0], bf[nt][1]);
        }
        __syncthreads();    // all reads of this buf done before refill
    }

#pragma unroll
    for (int mt = 0; mt < 2; mt++) {
#pragma unroll
        for (int i = 0; i < 2; i++) {
            int m = m0 + wm + mt * 16 + lr + i * 8;
#pragma unroll
            for (int nt = 0; nt < 8; nt++) {
                int n = n0 + wn + nt * 8 + lc * 2;
                float v0 = acc[mt][nt][i * 2 + 0];
                float v1 = acc[mt][nt][i * 2 + 1];
                if (bias) { v0 += bias[n]; v1 += bias[n + 1]; }
                if (!head_layout) {
                    *reinterpret_cast<float2*>(&C[(size_t)m * N + n]) = make_float2(v0, v1);
                } else {
                    int h = n >> 6, d = n & 63;
                    int bb = m >> 11, ss = m & 2047;
                    *reinterpret_cast<float2*>(
                        &C[(((size_t)(bb * NH + h) * S) + ss) * HD + d]) =
                        make_float2(tf(v0), tf(v1));   // pre-round for attention
                }
            }
        }
    }
}

__global__ __launch_bounds__(256) void qkv_gemm_kernel(
    const float* __restrict__ A,
    const float* __restrict__ Wq, const float* __restrict__ Wk, const float* __restrict__ Wv,
    float* __restrict__ q, float* __restrict__ k, float* __restrict__ v)
{
    extern __shared__ float sm[];
    const int z = blockIdx.z;
    const float* W = (z == 0) ? Wq : (z == 1) ? Wk : Wv;
    float* C       = (z == 0) ? q  : (z == 1) ? k  : v;
    gemm_body(A, W, C, nullptr, DIN, DOUT, 1, sm);
}

__global__ __launch_bounds__(256) void out_gemm_kernel(
    const float* __restrict__ A, const float* __restrict__ W,
    float* __restrict__ C, const float* __restrict__ bias)
{
    extern __shared__ float sm[];
    gemm_body(A, W, C, bias, DOUT, DOUT, 0, sm);
}

// ============================================================
// Causal flash attention (R16 version): BQ=128, BKV=64,
// split K/V cp.async with K prefetch overlapping PV mma;
// in-register softmax; qt reversed (long blocks first).
// ============================================================
constexpr int BQ  = 128;
constexpr int BKV = 64;
constexpr int PAD = 68;
constexpr float LOG2E = 1.4426950408889634f;
constexpr size_t ATTN_SMEM = (size_t)(BQ + BKV + BKV + BQ) * PAD * sizeof(float); // 104448

__global__ __launch_bounds__(256, 2) void attn_kernel(
    const float* __restrict__ Q, const float* __restrict__ Kp,
    const float* __restrict__ Vp, float* __restrict__ ctx)
{
    extern __shared__ float sm[];
    float (*Qs)[PAD] = reinterpret_cast<float(*)[PAD]>(sm);
    float (*Ks)[PAD] = reinterpret_cast<float(*)[PAD]>(sm + BQ * PAD);
    float (*Vs)[PAD] = reinterpret_cast<float(*)[PAD]>(sm + (BQ + BKV) * PAD);
    float (*Ps)[PAD] = reinterpret_cast<float(*)[PAD]>(sm + (BQ + 2 * BKV) * PAD);

    __shared__ float m_s[BQ], l_s[BQ];
    __shared__ float pmax[BQ][2], psum[BQ][2];

    const int tid  = threadIdx.x;
    const int warp = tid >> 5, lane = tid & 31;
    const int wm = (warp >> 1) * 32;
    const int wn = (warp & 1) * 32;
    const int wi = warp & 1;
    const int lr = lane >> 2, lc = lane & 3;
    const int qt = (gridDim.x - 1) - blockIdx.x;   // long blocks first
    const int bh = blockIdx.y;

    const float* qb = Q  + (size_t)bh * S * HD + (size_t)qt * BQ * HD;
    const float* kb = Kp + (size_t)bh * S * HD;
    const float* vb = Vp + (size_t)bh * S * HD;

    auto load_k = [&](int kt) {
        const float* kp_ = kb + (size_t)kt * BKV * HD;
#pragma unroll
        for (int p = 0; p < 4; p++) {
            int i = p * 256 + tid;
            int row = i >> 4, c4 = (i & 15) << 2;
            cp16(&Ks[row][c4], kp_ + row * HD + c4);
        }
        cp_commit();
    };
    auto load_v = [&](int kt) {
        const float* vp_ = vb + (size_t)kt * BKV * HD;
#pragma unroll
        for (int p = 0; p < 4; p++) {
            int i = p * 256 + tid;
            int row = i >> 4, c4 = (i & 15) << 2;
            cp16(&Vs[row][c4], vp_ + row * HD + c4);
        }
        cp_commit();
    };

    const float qscale = 0.125f * LOG2E;
    for (int i = tid; i < BQ * HD / 4; i += 256) {
        int row = i >> 4;
        int c4  = (i & 15) << 2;
        float4 v = *reinterpret_cast<const float4*>(qb + row * HD + c4);
        Qs[row][c4 + 0] = tf(v.x * qscale);
        Qs[row][c4 + 1] = tf(v.y * qscale);
        Qs[row][c4 + 2] = tf(v.z * qscale);
        Qs[row][c4 + 3] = tf(v.w * qscale);
    }
    if (tid < BQ) { m_s[tid] = -1e30f; l_s[tid] = 0.f; }

    float acc_o[2][4][4] = {};
    const int NKT = 2 * qt + 2;

    load_k(0);
    load_v(0);

    for (int kt = 0; kt < NKT; kt++) {
        cp_wait0();
        __syncthreads();                                   // sync 1

        float acc_s[2][4][4] = {};
#pragma unroll
        for (int kk = 0; kk < HD; kk += 8) {
            unsigned af[2][4], bf[4][2];
#pragma unroll
            for (int mt = 0; mt < 2; mt++) {
                int r = wm + mt * 16 + lr;
                af[mt][0] = __float_as_uint(Qs[r][kk + lc]);
                af[mt][1] = __float_as_uint(Qs[r + 8][kk + lc]);
                af[mt][2] = __float_as_uint(Qs[r][kk + lc + 4]);
                af[mt][3] = __float_as_uint(Qs[r + 8][kk + lc + 4]);
            }
#pragma unroll
            for (int nt = 0; nt < 4; nt++) {
                int c = wn + nt * 8 + lr;
                bf[nt][0] = __float_as_uint(Ks[c][kk + lc]);
                bf[nt][1] = __float_as_uint(Ks[c][kk + lc + 4]);
            }
#pragma unroll
            for (int mt = 0; mt < 2; mt++)
#pragma unroll
                for (int nt = 0; nt < 4; nt++)
                    mma_tf32(acc_s[mt][nt][0], acc_s[mt][nt][1],
                             acc_s[mt][nt][2], acc_s[mt][nt][3],
                             af[mt][0], af[mt][1], af[mt][2], af[mt][3],
                             bf[nt][0], bf[nt][1]);
        }

        if (kt >= 2 * qt) {
            int cbase = kt * BKV - qt * BQ;
#pragma unroll
            for (int mt = 0; mt < 2; mt++) {
                int r0 = wm + mt * 16 + lr;
#pragma unroll
                for (int nt = 0; nt < 4; nt++) {
                    int c0 = cbase + wn + nt * 8 + 2 * lc;
                    if (c0 > r0)         acc_s[mt][nt][0] = -1e30f;
                    if (c0 + 1 > r0)     acc_s[mt][nt][1] = -1e30f;
                    if (c0 > r0 + 8)     acc_s[mt][nt][2] = -1e30f;
                    if (c0 + 1 > r0 + 8) acc_s[mt][nt][3] = -1e30f;
                }
            }
        }

#pragma unroll
        for (int mt = 0; mt < 2; mt++) {
            float m0 = -1e30f, m1 = -1e30f;
#pragma unroll
            for (int nt = 0; nt < 4; nt++) {
                m0 = fmaxf(m0, fmaxf(acc_s[mt][nt][0], acc_s[mt][nt][1]));
                m1 = fmaxf(m1, fmaxf(acc_s[mt][nt][2], acc_s[mt][nt][3]));
            }
            m0 = fmaxf(m0, __shfl_xor_sync(0xffffffffu, m0, 1));
            m0 = fmaxf(m0, __shfl_xor_sync(0xffffffffu, m0, 2));
            m1 = fmaxf(m1, __shfl_xor_sync(0xffffffffu, m1, 1));
            m1 = fmaxf(m1, __shfl_xor_sync(0xffffffffu, m1, 2));
            if (lc == 0) {
                pmax[wm + mt * 16 + lr][wi] = m0;
                pmax[wm + mt * 16 + lr + 8][wi] = m1;
            }
        }
        __syncthreads();                                   // sync 2

        float alpha[2][2], mxv[2][2];
#pragma unroll
        for (int mt = 0; mt < 2; mt++) {
#pragma unroll
            for (int i = 0; i < 2; i++) {
                int r = wm + mt * 16 + lr + i * 8;
                float mo = m_s[r];
                float mx = fmaxf(mo, fmaxf(pmax[r][0], pmax[r][1]));
                mxv[mt][i] = mx;
                alpha[mt][i] = exp2f(mo - mx);
                float sum = 0.f;
#pragma unroll
                for (int nt = 0; nt < 4; nt++) {
                    float p0 = tf(exp2f(acc_s[mt][nt][i * 2 + 0] - mx));
                    float p1 = tf(exp2f(acc_s[mt][nt][i * 2 + 1] - mx));
                    sum += p0 + p1;
                    *reinterpret_cast<float2*>(&Ps[r][wn + nt * 8 + 2 * lc]) =
                        make_float2(p0, p1);
                }
                sum += __shfl_xor_sync(0xffffffffu, sum, 1);
                sum += __shfl_xor_sync(0xffffffffu, sum, 2);
                if (lc == 0) psum[r][wi] = sum;
            }
        }
        __syncthreads();                                   // sync 3

        // K no longer needed: overlap next K load with the PV mma
        if (kt + 1 < NKT) load_k(kt + 1);

        if (wi == 0 && lc == 0) {
#pragma unroll
            for (int mt = 0; mt < 2; mt++)
#pragma unroll
                for (int i = 0; i < 2; i++) {
                    int r = wm + mt * 16 + lr + i * 8;
                    l_s[r] = l_s[r] * alpha[mt][i] + psum[r][0] + psum[r][1];
                    m_s[r] = mxv[mt][i];
                }
        }
#pragma unroll
        for (int mt = 0; mt < 2; mt++)
#pragma unroll
            for (int nt = 0; nt < 4; nt++) {
                acc_o[mt][nt][0] *= alpha[mt][0]; acc_o[mt][nt][1] *= alpha[mt][0];
                acc_o[mt][nt][2] *= alpha[mt][1]; acc_o[mt][nt][3] *= alpha[mt][1];
            }
#pragma unroll
        for (int kk = 0; kk < BKV; kk += 8) {
            unsigned af[2][4], bf[4][2];
#pragma unroll
            for (int mt = 0; mt < 2; mt++) {
                int r = wm + mt * 16 + lr;
                af[mt][0] = __float_as_uint(Ps[r][kk + lc]);
                af[mt][1] = __float_as_uint(Ps[r + 8][kk + lc]);
                af[mt][2] = __float_as_uint(Ps[r][kk + lc + 4]);
                af[mt][3] = __float_as_uint(Ps[r + 8][kk + lc + 4]);
            }
#pragma unroll
            for (int nt = 0; nt < 4; nt++) {
                int c = wn + nt * 8 + lr;
                bf[nt][0] = __float_as_uint(Vs[kk + lc][c]);
                bf[nt][1] = __float_as_uint(Vs[kk + lc + 4][c]);
            }
#pragma unroll
            for (int mt = 0; mt < 2; mt++)
#pragma unroll
                for (int nt = 0; nt < 4; nt++)
                    mma_tf32(acc_o[mt][nt][0], acc_o[mt][nt][1],
                             acc_o[mt][nt][2], acc_o[mt][nt][3],
                             af[mt][0], af[mt][1], af[mt][2], af[mt][3],
                             bf[nt][0], bf[nt][1]);
        }
        __syncthreads();                                   // sync 4

        // V free now: issue next V load (waited at loop top)
        if (kt + 1 < NKT) load_v(kt + 1);
    }

    const int h  = bh % NH;
    const int bb = bh / NH;
#pragma unroll
    for (int mt = 0; mt < 2; mt++) {
#pragma unroll
        for (int i = 0; i < 2; i++) {
            int r = wm + mt * 16 + lr + i * 8;
            float inv = 1.0f / l_s[r];
            size_t rowp = (size_t)(bb * S + qt * BQ + r) * DOUT + h * HD;
#pragma unroll
            for (int nt = 0; nt < 4; nt++) {
                int c = wn + nt * 8 + lc * 2;
                *reinterpret_cast<float2*>(&ctx[rowp + c]) =
                    make_float2(tf(acc_o[mt][nt][i * 2 + 0] * inv),
                                tf(acc_o[mt][nt][i * 2 + 1] * inv));
            }
        }
    }
}

}  // namespace

extern "C" void kernel_launch(void* const* d_in, const int* in_sizes, int n_in,
                              void* d_out, int out_size)
{
    (void)in_sizes; (void)n_in; (void)out_size;
    const float* x  = (const float*)d_in[0];
    const float* Wq = (const float*)d_in[1];
    const float* Wk = (const float*)d_in[2];
    const float* Wv = (const float*)d_in[3];
    const float* Wo = (const float*)d_in[4];
    const float* bo = (const float*)d_in[5];
    float* out = (float*)d_out;

    float *qp, *kp, *vp, *cp, *xc, *wq, *wk, *wv, *wo;
    cudaGetSymbolAddress((void**)&qp, g_q);
    cudaGetSymbolAddress((void**)&kp, g_k);
    cudaGetSymbolAddress((void**)&vp, g_v);
    cudaGetSymbolAddress((void**)&cp, g_ctx);
    cudaGetSymbolAddress((void**)&xc, g_xc);
    cudaGetSymbolAddress((void**)&wq, g_wq);
    cudaGetSymbolAddress((void**)&wk, g_wk);
    cudaGetSymbolAddress((void**)&wv, g_wv);
    cudaGetSymbolAddress((void**)&wo, g_wo);

    cudaFuncSetAttribute(qkv_gemm_kernel,
                         cudaFuncAttributeMaxDynamicSharedMemorySize, (int)GEMM_SMEM);
    cudaFuncSetAttribute(out_gemm_kernel,
                         cudaFuncAttributeMaxDynamicSharedMemorySize, (int)GEMM_SMEM);
    cudaFuncSetAttribute(attn_kernel,
                         cudaFuncAttributeMaxDynamicSharedMemorySize, (int)ATTN_SMEM);

    // ---- fused tf32 rounding pre-pass (1 launch) ----
    cvt_all_kernel<<<XB + 4 * WB, 256>>>(x, xc, Wq, wq, Wk, wk, Wv, wv, Wo, wo);

    // ---- fused QKV projections (outputs tf32-rounded) ----
    dim3 qkv_grid(DOUT / GBN, M / GBM, 3);  // (8, 64, 3)
    qkv_gemm_kernel<<<qkv_grid, 256, GEMM_SMEM>>>(xc, wq, wk, wv, qp, kp, vp);

    // ---- attention ----
    dim3 attn_grid(S / BQ, B * NH);         // (16, 64)
    attn_kernel<<<attn_grid, 256, ATTN_SMEM>>>(qp, kp, vp, cp);

    // ---- output projection ----
    dim3 out_grid(DOUT / GBN, M / GBM);     // (8, 64)
    out_gemm_kernel<<<out_grid, 256, GEMM_SMEM>>>(cp, wo, out, bo);
}